// round 15
// baseline (speedup 1.0000x reference)
#include <cuda_runtime.h>
#include <cuda_bf16.h>
#include <cstdint>

#define Hh 128
#define DAa 128
#define DMm 64
#define NA_MAX 200000
#define NM_MAX 100000
#define E_MAX 1000000

// ---------------- device scratch (allocation-free: device globals) ----------------
__device__ float         g_b1[Hh];
__device__ float         g_b2[Hh];
__device__ __nv_bfloat16 g_W1h[Hh * DAa];        // 32 KB
__device__ __nv_bfloat16 g_W2h[Hh * DMm];        // 16 KB
__device__ __nv_bfloat16 g_m2[NM_MAX * Hh];      // 25.6 MB  m2 (bf16)
__device__ __nv_bfloat16 g_acch[NA_MAX * Hh];    // 51.2 MB  proj+bias staged in bf16
__device__ int           g_deg[NA_MAX];
__device__ int           g_off[NA_MAX];
__device__ int           g_cnt[NA_MAX];
__device__ int2          g_epk[E_MAX];           // dst-grouped (src, w_bits)
__device__ int           g_bsum[256];
__device__ int           g_bofs[256];

__device__ __forceinline__ uint32_t smem_u32(const void* p) {
    uint32_t a;
    asm("{ .reg .u64 t; cvta.to.shared.u64 t, %1; cvt.u32.u64 %0, t; }" : "=r"(a) : "l"(p));
    return a;
}

#define LDMATRIX_X4(r0, r1, r2, r3, addr) \
    asm volatile("ldmatrix.sync.aligned.m8n8.x4.shared.b16 {%0,%1,%2,%3}, [%4];" \
                 : "=r"(r0), "=r"(r1), "=r"(r2), "=r"(r3) : "r"(addr))

#define MMA_BF16(c, a0, a1, a2, a3, b0, b1) \
    asm volatile("mma.sync.aligned.m16n8k16.row.col.f32.bf16.bf16.f32 " \
                 "{%0,%1,%2,%3}, {%4,%5,%6,%7}, {%8,%9}, {%0,%1,%2,%3};" \
                 : "+f"((c)[0]), "+f"((c)[1]), "+f"((c)[2]), "+f"((c)[3]) \
                 : "r"(a0), "r"(a1), "r"(a2), "r"(a3), "r"(b0), "r"(b1))

// ---------------- fold2: W2 = Wc2 @ Wr_ma, b2 (small, gates GEMM2) ----------------
__global__ void fold2_kernel(const float* __restrict__ Wc_a,
                             const float* __restrict__ Wr_ma,
                             const float* __restrict__ br_ma) {
    int h = blockIdx.x;        // 0..127
    int d = threadIdx.x;       // 0..63
    const float* wc2 = Wc_a + h * 256 + 128;
    float t_a = 0.f, t_b = 0.f;
    #pragma unroll 8
    for (int k = 0; k < 128; k += 2) {
        t_a += wc2[k]     * Wr_ma[k * DMm + d];
        t_b += wc2[k + 1] * Wr_ma[(k + 1) * DMm + d];
    }
    g_W2h[h * DMm + d] = __float2bfloat16(t_a + t_b);
    if (d == 0) {
        float t2 = 0.f;
        for (int k = 0; k < 128; ++k) t2 += wc2[k] * br_ma[k];
        g_b2[h] = t2;
    }
}

// ---------------- fold1: W1 = Wc1 @ Wp_a, b1 (gates GEMM3) ----------------
__global__ void fold1_kernel(const float* __restrict__ Wc_a,
                             const float* __restrict__ Wp_a,
                             const float* __restrict__ bp_a,
                             const float* __restrict__ bc_a) {
    int h = blockIdx.x;        // 0..127
    int d = threadIdx.x;       // 0..127
    const float* wc1 = Wc_a + h * 256;
    float s_a = 0.f, s_b = 0.f;
    #pragma unroll 8
    for (int k = 0; k < 128; k += 2) {
        s_a += wc1[k]     * Wp_a[k * DAa + d];
        s_b += wc1[k + 1] * Wp_a[(k + 1) * DAa + d];
    }
    g_W1h[h * DAa + d] = __float2bfloat16(s_a + s_b);
    if (d == 0) {
        float t1 = bc_a[h];
        for (int k = 0; k < 128; ++k) t1 += wc1[k] * bp_a[k];
        g_b1[h] = t1;
    }
}

// ---------------- kernels 2/3: warp-MMA GEMM  C[M,128] = bf16(A[M,K] @ Wh^T + bias) ----
template <int K>
__global__ void __launch_bounds__(256)
mma_gemm_kernel(const float* __restrict__ A, int M,
                const __nv_bfloat16* __restrict__ W,     // [128 x K] bf16 row-major
                const float* __restrict__ bias,
                __nv_bfloat16* __restrict__ Cout) {
    constexpr int RS = K * 2 + 16;           // padded row stride (bytes)
    constexpr int TILE_B = 128 * RS;
    constexpr int WPR = K / 2;               // 4-byte words per row
    constexpr int QPR = K / 4;               // 16-byte quads per row
    extern __shared__ char smem[];
    char*  smA   = smem;
    char*  smW   = smem + TILE_B;
    float* sbias = (float*)(smem + 2 * TILE_B);

    const int tid = threadIdx.x, wid = tid >> 5, lane = tid & 31;
    const int row0 = blockIdx.x * 128;

    // stage W (bf16, float4-width copies: 8 elems per op)
    for (int idx = tid; idx < 128 * (WPR / 4); idx += 256) {
        int r = idx / (WPR / 4), p = idx - r * (WPR / 4);
        *(uint4*)(smW + r * RS + p * 16) = ((const uint4*)W)[idx];
    }
    // stage A with fp32->bf16 conversion (float4 loads: 4 elems per op)
    for (int idx = tid; idx < 128 * QPR; idx += 256) {
        int r = idx / QPR, p = idx - r * QPR;
        int gr = row0 + r;
        float4 av = (gr < M) ? ((const float4*)(A + (size_t)gr * K))[p]
                             : make_float4(0.f, 0.f, 0.f, 0.f);
        uint32_t lo, hi;
        asm("cvt.rn.bf16x2.f32 %0, %1, %2;" : "=r"(lo) : "f"(av.y), "f"(av.x));
        asm("cvt.rn.bf16x2.f32 %0, %1, %2;" : "=r"(hi) : "f"(av.w), "f"(av.z));
        *(uint2*)(smA + r * RS + p * 8) = make_uint2(lo, hi);
    }
    if (tid < 128) sbias[tid] = bias[tid];
    __syncthreads();

    const uint32_t aBase = smem_u32(smA)
        + (uint32_t)(wid * 16 + (lane & 15)) * RS + (uint32_t)(lane >> 4) * 16;
    const uint32_t bBase = smem_u32(smW)
        + (uint32_t)((lane & 7) + ((lane >> 4) << 3)) * RS
        + (uint32_t)((lane >> 3) & 1) * 16;

    float acc[16][4];
    #pragma unroll
    for (int i = 0; i < 16; ++i)
        #pragma unroll
        for (int j = 0; j < 4; ++j) acc[i][j] = 0.f;

    #pragma unroll
    for (int ks = 0; ks < K / 16; ++ks) {
        uint32_t a0, a1, a2, a3;
        LDMATRIX_X4(a0, a1, a2, a3, aBase + (uint32_t)ks * 32);
        #pragma unroll
        for (int jp = 0; jp < 8; ++jp) {
            uint32_t b0, b1, b2, b3;
            LDMATRIX_X4(b0, b1, b2, b3, bBase + (uint32_t)(jp * 16) * RS + (uint32_t)ks * 32);
            MMA_BF16(acc[2 * jp],     a0, a1, a2, a3, b0, b1);
            MMA_BF16(acc[2 * jp + 1], a0, a1, a2, a3, b2, b3);
        }
    }

    const int g = lane >> 2, t = lane & 3;
    const int r_lo = row0 + wid * 16 + g;
    const int r_hi = r_lo + 8;
    const bool lo_ok = r_lo < M, hi_ok = r_hi < M;

    #pragma unroll
    for (int nt = 0; nt < 16; ++nt) {
        int col = nt * 8 + 2 * t;
        float bx = sbias[col], by = sbias[col + 1];
        uint32_t plo, phi;
        asm("cvt.rn.bf16x2.f32 %0, %1, %2;" : "=r"(plo)
            : "f"(acc[nt][1] + by), "f"(acc[nt][0] + bx));
        asm("cvt.rn.bf16x2.f32 %0, %1, %2;" : "=r"(phi)
            : "f"(acc[nt][3] + by), "f"(acc[nt][2] + bx));
        if (lo_ok) *(uint32_t*)(Cout + (size_t)r_lo * 128 + col) = plo;
        if (hi_ok) *(uint32_t*)(Cout + (size_t)r_hi * 128 + col) = phi;
    }
}

// ---------------- CSR build ----------------
__global__ void hist_kernel(const int* __restrict__ dst, int E, int* __restrict__ deg) {
    int i = blockIdx.x * blockDim.x + threadIdx.x;
    if (i < E) atomicAdd(&deg[dst[i]], 1);
}

__global__ void scan1_kernel(const int* __restrict__ in, int n,
                             int* __restrict__ out, int* __restrict__ bsum) {
    __shared__ int sh[1024];
    int i = blockIdx.x * 1024 + threadIdx.x;
    int v = (i < n) ? in[i] : 0;
    sh[threadIdx.x] = v;
    __syncthreads();
    #pragma unroll
    for (int off = 1; off < 1024; off <<= 1) {
        int t = (threadIdx.x >= off) ? sh[threadIdx.x - off] : 0;
        __syncthreads();
        sh[threadIdx.x] += t;
        __syncthreads();
    }
    if (i < n) out[i] = sh[threadIdx.x] - v;
    if (bsum && threadIdx.x == 1023) bsum[blockIdx.x] = sh[1023];
}

__global__ void scan3_kernel(int* __restrict__ out, int n, const int* __restrict__ bofs) {
    int i = blockIdx.x * blockDim.x + threadIdx.x;
    if (i < n) out[i] += bofs[i >> 10];
}

__global__ void place_kernel(const int* __restrict__ src, const int* __restrict__ dst,
                             const float* __restrict__ w, int E,
                             const int* __restrict__ off, int* __restrict__ cnt,
                             int2* __restrict__ epk) {
    int i = blockIdx.x * blockDim.x + threadIdx.x;
    if (i >= E) return;
    int d = dst[i];
    int p = off[d] + atomicAdd(&cnt[d], 1);
    epk[p] = make_int2(src[i], __float_as_int(w[i]));
}

// ---------------- gather-reduce + head: one HALF-WARP per account, 16B lanes ----------
__global__ void __launch_bounds__(256)
gather_head_kernel(const __nv_bfloat16* __restrict__ acch,
                   const int* __restrict__ off,
                   const int2* __restrict__ epk,
                   const __nv_bfloat16* __restrict__ m2,
                   const float* __restrict__ Wo,
                   const float* __restrict__ bo,
                   float* __restrict__ out,
                   int na0, int na1, int NA, int E) {
    const int tid  = threadIdx.x;
    const int lane = tid & 31;
    const int hw   = lane >> 4;                    // half-warp id 0/1
    const int sl   = lane & 15;                    // sub-lane 0..15
    const int acct = na0 + ((blockIdx.x * blockDim.x + tid) >> 5) * 2 + hw;
    if (acct >= na1) return;

    const int a = off[acct];
    const int b = (acct + 1 < NA) ? off[acct + 1] : E;

    float z0, z1, z2, z3, z4, z5, z6, z7;
    {
        uint4 q = *(const uint4*)((const char*)acch + (size_t)acct * 256 + sl * 16);
        float2 f0 = __bfloat1622float2(*reinterpret_cast<__nv_bfloat162*>(&q.x));
        float2 f1 = __bfloat1622float2(*reinterpret_cast<__nv_bfloat162*>(&q.y));
        float2 f2 = __bfloat1622float2(*reinterpret_cast<__nv_bfloat162*>(&q.z));
        float2 f3 = __bfloat1622float2(*reinterpret_cast<__nv_bfloat162*>(&q.w));
        z0 = f0.x; z1 = f0.y; z2 = f1.x; z3 = f1.y;
        z4 = f2.x; z5 = f2.y; z6 = f3.x; z7 = f3.y;
    }

    const uint32_t sl16 = (uint32_t)sl * 16u;
    int e = a;
    #define ACC_EDGE(P, Q) do { \
        float wf = __int_as_float((P).y); \
        float2 f0 = __bfloat1622float2(*reinterpret_cast<__nv_bfloat162*>(&(Q).x)); \
        float2 f1 = __bfloat1622float2(*reinterpret_cast<__nv_bfloat162*>(&(Q).y)); \
        float2 f2 = __bfloat1622float2(*reinterpret_cast<__nv_bfloat162*>(&(Q).z)); \
        float2 f3 = __bfloat1622float2(*reinterpret_cast<__nv_bfloat162*>(&(Q).w)); \
        z0 = fmaf(f0.x, wf, z0); z1 = fmaf(f0.y, wf, z1); \
        z2 = fmaf(f1.x, wf, z2); z3 = fmaf(f1.y, wf, z3); \
        z4 = fmaf(f2.x, wf, z4); z5 = fmaf(f2.y, wf, z5); \
        z6 = fmaf(f3.x, wf, z6); z7 = fmaf(f3.y, wf, z7); \
    } while (0)

    for (; e + 4 <= b; e += 4) {
        int2 p0 = __ldg(&epk[e + 0]);
        int2 p1 = __ldg(&epk[e + 1]);
        int2 p2 = __ldg(&epk[e + 2]);
        int2 p3 = __ldg(&epk[e + 3]);
        uint4 q0 = *(const uint4*)((const char*)m2 + (size_t)p0.x * 256 + sl16);
        uint4 q1 = *(const uint4*)((const char*)m2 + (size_t)p1.x * 256 + sl16);
        uint4 q2 = *(const uint4*)((const char*)m2 + (size_t)p2.x * 256 + sl16);
        uint4 q3 = *(const uint4*)((const char*)m2 + (size_t)p3.x * 256 + sl16);
        ACC_EDGE(p0, q0); ACC_EDGE(p1, q1); ACC_EDGE(p2, q2); ACC_EDGE(p3, q3);
    }
    for (; e < b; ++e) {
        int2 pk = __ldg(&epk[e]);
        uint4 q = *(const uint4*)((const char*)m2 + (size_t)pk.x * 256 + sl16);
        ACC_EDGE(pk, q);
    }
    #undef ACC_EDGE

    const float4 w0 = ((const float4*)Wo)[sl * 2];
    const float4 w1 = ((const float4*)Wo)[sl * 2 + 1];
    float p = fmaxf(z0, 0.f) * w0.x + fmaxf(z1, 0.f) * w0.y +
              fmaxf(z2, 0.f) * w0.z + fmaxf(z3, 0.f) * w0.w +
              fmaxf(z4, 0.f) * w1.x + fmaxf(z5, 0.f) * w1.y +
              fmaxf(z6, 0.f) * w1.z + fmaxf(z7, 0.f) * w1.w;
    #pragma unroll
    for (int o = 8; o > 0; o >>= 1)
        p += __shfl_xor_sync(0xFFFFFFFFu, p, o);
    if (sl == 0) {
        float zz = p + bo[0];
        out[acct] = 1.f / (1.f + expf(-zz));
    }
}

// ---------------- launch (fork-join + 2-way GEMM3/gather pipeline) ----------------
extern "C" void kernel_launch(void* const* d_in, const int* in_sizes, int n_in,
                              void* d_out, int out_size) {
    const float* x_account  = (const float*)d_in[0];
    const float* x_merchant = (const float*)d_in[1];
    const int*   e_ma_src = (const int*)d_in[5];
    const int*   e_ma_dst = (const int*)d_in[6];
    const float* e_ma_w   = (const float*)d_in[7];
    const float* Wp_a  = (const float*)d_in[8];
    const float* bp_a  = (const float*)d_in[9];
    const float* Wr_ma = (const float*)d_in[14];
    const float* br_ma = (const float*)d_in[15];
    const float* Wc_a  = (const float*)d_in[16];
    const float* bc_a  = (const float*)d_in[17];
    const float* Wo = (const float*)d_in[20];
    const float* bo = (const float*)d_in[21];
    float* out = (float*)d_out;

    const int NA = in_sizes[0] / DAa;   // 200000
    const int NM = in_sizes[1] / DMm;   // 100000
    const int E  = in_sizes[5];         // 1000000

    float *pb1, *pb2;
    __nv_bfloat16 *pW1h, *pW2h, *pm2, *pacch;
    int *pdeg, *poff, *pcnt, *pbsum, *pbofs;
    int2 *pepk;
    cudaGetSymbolAddress((void**)&pb1, g_b1);
    cudaGetSymbolAddress((void**)&pb2, g_b2);
    cudaGetSymbolAddress((void**)&pW1h, g_W1h);
    cudaGetSymbolAddress((void**)&pW2h, g_W2h);
    cudaGetSymbolAddress((void**)&pm2, g_m2);
    cudaGetSymbolAddress((void**)&pacch, g_acch);
    cudaGetSymbolAddress((void**)&pdeg, g_deg);
    cudaGetSymbolAddress((void**)&poff, g_off);
    cudaGetSymbolAddress((void**)&pcnt, g_cnt);
    cudaGetSymbolAddress((void**)&pbsum, g_bsum);
    cudaGetSymbolAddress((void**)&pbofs, g_bofs);
    cudaGetSymbolAddress((void**)&pepk, g_epk);

    constexpr int SMEM_K128 = 2 * 128 * (128 * 2 + 16) + 512;   // 70144 B
    constexpr int SMEM_K64  = 2 * 128 * (64 * 2 + 16) + 512;    // 37376 B
    cudaFuncSetAttribute(mma_gemm_kernel<128>,
                         cudaFuncAttributeMaxDynamicSharedMemorySize, SMEM_K128);
    cudaFuncSetAttribute(mma_gemm_kernel<64>,
                         cudaFuncAttributeMaxDynamicSharedMemorySize, SMEM_K64);

    static cudaStream_t sCsr = [] { cudaStream_t s;
        cudaStreamCreateWithFlags(&s, cudaStreamNonBlocking); return s; }();
    static cudaStream_t sM2 = [] { cudaStream_t s;
        cudaStreamCreateWithFlags(&s, cudaStreamNonBlocking); return s; }();
    static cudaStream_t sGat = [] { cudaStream_t s;
        cudaStreamCreateWithFlags(&s, cudaStreamNonBlocking); return s; }();
    static cudaEvent_t evRoot = [] { cudaEvent_t e;
        cudaEventCreateWithFlags(&e, cudaEventDisableTiming); return e; }();
    static cudaEvent_t evF2 = [] { cudaEvent_t e;
        cudaEventCreateWithFlags(&e, cudaEventDisableTiming); return e; }();
    static cudaEvent_t evCsr = [] { cudaEvent_t e;
        cudaEventCreateWithFlags(&e, cudaEventDisableTiming); return e; }();
    static cudaEvent_t evM2 = [] { cudaEvent_t e;
        cudaEventCreateWithFlags(&e, cudaEventDisableTiming); return e; }();
    static cudaEvent_t evG3a = [] { cudaEvent_t e;
        cudaEventCreateWithFlags(&e, cudaEventDisableTiming); return e; }();
    static cudaEvent_t evG3b = [] { cudaEvent_t e;
        cudaEventCreateWithFlags(&e, cudaEventDisableTiming); return e; }();
    static cudaEvent_t evGat = [] { cudaEvent_t e;
        cudaEventCreateWithFlags(&e, cudaEventDisableTiming); return e; }();

    // GEMM3 split point (multiple of 128 rows)
    const int half = ((NA / 2 + 127) / 128) * 128;     // 100096

    // Fork from the capture (default) stream
    cudaEventRecord(evRoot, 0);
    cudaStreamWaitEvent(sCsr, evRoot, 0);
    cudaStreamWaitEvent(sM2, evRoot, 0);
    cudaStreamWaitEvent(sGat, evRoot, 0);

    // --- branch A (sCsr): CSR build ---
    cudaMemsetAsync(pdeg, 0, (size_t)NA * sizeof(int), sCsr);
    cudaMemsetAsync(pcnt, 0, (size_t)NA * sizeof(int), sCsr);
    hist_kernel<<<(E + 255) / 256, 256, 0, sCsr>>>(e_ma_dst, E, pdeg);
    {
        int nblk = (NA + 1023) / 1024;           // 196
        scan1_kernel<<<nblk, 1024, 0, sCsr>>>(pdeg, NA, poff, pbsum);
        scan1_kernel<<<1, 1024, 0, sCsr>>>(pbsum, nblk, pbofs, nullptr);
        scan3_kernel<<<(NA + 255) / 256, 256, 0, sCsr>>>(poff, NA, pbofs);
    }
    place_kernel<<<(E + 255) / 256, 256, 0, sCsr>>>(e_ma_src, e_ma_dst, e_ma_w,
                                                    E, poff, pcnt, pepk);
    cudaEventRecord(evCsr, sCsr);

    // --- branch C (sM2): fold2 -> GEMM2 (starts immediately) ---
    fold2_kernel<<<128, 64, 0, sM2>>>(Wc_a, Wr_ma, br_ma);
    mma_gemm_kernel<64><<<(NM + 127) / 128, 256, SMEM_K64, sM2>>>(
        x_merchant, NM, pW2h, pb2, pm2);
    cudaEventRecord(evM2, sM2);

    // --- branch B (default): fold1 -> GEMM3 halves ---
    fold1_kernel<<<128, 128>>>(Wc_a, Wp_a, bp_a, bc_a);
    mma_gemm_kernel<128><<<half / 128, 256, SMEM_K128>>>(
        x_account, half, pW1h, pb1, pacch);
    cudaEventRecord(evG3a, 0);
    mma_gemm_kernel<128><<<(NA - half + 127) / 128, 256, SMEM_K128>>>(
        x_account + (size_t)half * DAa, NA - half, pW1h, pb1,
        pacch + (size_t)half * Hh);
    cudaEventRecord(evG3b, 0);

    // --- branch D (sGat): gather+head pipelined against GEMM3 half 2 ---
    cudaStreamWaitEvent(sGat, evCsr, 0);
    cudaStreamWaitEvent(sGat, evM2, 0);
    cudaStreamWaitEvent(sGat, evG3a, 0);
    gather_head_kernel<<<(half + 15) / 16, 256, 0, sGat>>>(
        pacch, poff, pepk, pm2, Wo, bo, out, 0, half, NA, E);
    cudaStreamWaitEvent(sGat, evG3b, 0);
    gather_head_kernel<<<(NA - half + 15) / 16, 256, 0, sGat>>>(
        pacch, poff, pepk, pm2, Wo, bo, out, half, NA, NA, E);
    cudaEventRecord(evGat, sGat);

    // --- join back to capture stream ---
    cudaStreamWaitEvent(0, evGat, 0);
}

// round 17
// speedup vs baseline: 1.0818x; 1.0818x over previous
#include <cuda_runtime.h>
#include <cuda_bf16.h>
#include <cstdint>

#define Hh 128
#define DAa 128
#define DMm 64
#define NA_MAX 200000
#define NM_MAX 100000
#define E_MAX 1000000

// ---------------- device scratch (allocation-free: device globals) ----------------
__device__ float         g_b1[Hh];
__device__ float         g_b2[Hh];
__device__ __nv_bfloat16 g_W1h[Hh * DAa];        // 32 KB
__device__ __nv_bfloat16 g_W2h[Hh * DMm];        // 16 KB
__device__ __nv_bfloat16 g_m2[NM_MAX * Hh];      // 25.6 MB  m2 (bf16)      — keep in L2
__device__ __nv_bfloat16 g_acch[NA_MAX * Hh];    // 51.2 MB  proj (bf16)    — keep in L2
__device__ int           g_deg[NA_MAX];
__device__ int           g_off[NA_MAX];
__device__ int           g_cnt[NA_MAX];
__device__ int2          g_epk[E_MAX];           // 8 MB dst-grouped (src,w)— keep in L2
__device__ int           g_bsum[256];
__device__ int           g_bofs[256];

__device__ __forceinline__ uint32_t smem_u32(const void* p) {
    uint32_t a;
    asm("{ .reg .u64 t; cvta.to.shared.u64 t, %1; cvt.u32.u64 %0, t; }" : "=r"(a) : "l"(p));
    return a;
}

#define LDMATRIX_X4(r0, r1, r2, r3, addr) \
    asm volatile("ldmatrix.sync.aligned.m8n8.x4.shared.b16 {%0,%1,%2,%3}, [%4];" \
                 : "=r"(r0), "=r"(r1), "=r"(r2), "=r"(r3) : "r"(addr))

#define MMA_BF16(c, a0, a1, a2, a3, b0, b1) \
    asm volatile("mma.sync.aligned.m16n8k16.row.col.f32.bf16.bf16.f32 " \
                 "{%0,%1,%2,%3}, {%4,%5,%6,%7}, {%8,%9}, {%0,%1,%2,%3};" \
                 : "+f"((c)[0]), "+f"((c)[1]), "+f"((c)[2]), "+f"((c)[3]) \
                 : "r"(a0), "r"(a1), "r"(a2), "r"(a3), "r"(b0), "r"(b1))

// ---------------- kernel 1: fold the linear chain ----------------
__global__ void fold_kernel(const float* __restrict__ Wc_a,
                            const float* __restrict__ Wp_a,
                            const float* __restrict__ Wr_ma,
                            const float* __restrict__ bp_a,
                            const float* __restrict__ bc_a,
                            const float* __restrict__ br_ma) {
    int h = blockIdx.x;        // 0..127
    int d = threadIdx.x;       // 0..127
    const float* wc1 = Wc_a + h * 256;
    const float* wc2 = wc1 + 128;

    float s = 0.f;
    #pragma unroll 8
    for (int k = 0; k < 128; ++k) s += wc1[k] * Wp_a[k * DAa + d];
    g_W1h[h * DAa + d] = __float2bfloat16(s);

    if (d < DMm) {
        float s2 = 0.f;
        #pragma unroll 8
        for (int k = 0; k < 128; ++k) s2 += wc2[k] * Wr_ma[k * DMm + d];
        g_W2h[h * DMm + d] = __float2bfloat16(s2);
    }
    if (d == 0) {
        float t1 = bc_a[h], t2 = 0.f;
        for (int k = 0; k < 128; ++k) {
            t1 += wc1[k] * bp_a[k];
            t2 += wc2[k] * br_ma[k];
        }
        g_b1[h] = t1;
        g_b2[h] = t2;
    }
}

// ---------------- kernels 2/3: warp-MMA GEMM  C[M,128] = bf16(A[M,K] @ Wh^T + bias) ----
// A is a read-once stream: loaded with __ldcs (evict-first) so it does not evict
// the retained L2 set (acch / m2 / epk) needed by the gather phase.
template <int K>
__global__ void __launch_bounds__(256)
mma_gemm_kernel(const float* __restrict__ A, int M,
                const __nv_bfloat16* __restrict__ W,     // [128 x K] bf16 row-major
                const float* __restrict__ bias,
                __nv_bfloat16* __restrict__ Cout) {
    constexpr int RS = K * 2 + 16;           // padded row stride (bytes)
    constexpr int TILE_B = 128 * RS;
    constexpr int WPR = K / 2;               // 4-byte words per row
    extern __shared__ char smem[];
    char*  smA   = smem;
    char*  smW   = smem + TILE_B;
    float* sbias = (float*)(smem + 2 * TILE_B);

    const int tid = threadIdx.x, wid = tid >> 5, lane = tid & 31;
    const int row0 = blockIdx.x * 128;

    for (int idx = tid; idx < 128 * WPR; idx += 256) {
        int r = idx / WPR, p = idx - r * WPR;
        *(uint32_t*)(smW + r * RS + p * 4) = ((const uint32_t*)W)[idx];
    }
    for (int idx = tid; idx < 128 * WPR; idx += 256) {
        int r = idx / WPR, p = idx - r * WPR;
        int gr = row0 + r;
        float2 av = (gr < M) ? __ldcs((const float2*)(A + (size_t)gr * K) + p)
                             : make_float2(0.f, 0.f);
        uint32_t pv;
        asm("cvt.rn.bf16x2.f32 %0, %1, %2;" : "=r"(pv) : "f"(av.y), "f"(av.x));
        *(uint32_t*)(smA + r * RS + p * 4) = pv;
    }
    if (tid < 128) sbias[tid] = bias[tid];
    __syncthreads();

    const uint32_t aBase = smem_u32(smA)
        + (uint32_t)(wid * 16 + (lane & 15)) * RS + (uint32_t)(lane >> 4) * 16;
    const uint32_t bBase = smem_u32(smW)
        + (uint32_t)((lane & 7) + ((lane >> 4) << 3)) * RS
        + (uint32_t)((lane >> 3) & 1) * 16;

    float acc[16][4];
    #pragma unroll
    for (int i = 0; i < 16; ++i)
        #pragma unroll
        for (int j = 0; j < 4; ++j) acc[i][j] = 0.f;

    #pragma unroll
    for (int ks = 0; ks < K / 16; ++ks) {
        uint32_t a0, a1, a2, a3;
        LDMATRIX_X4(a0, a1, a2, a3, aBase + (uint32_t)ks * 32);
        #pragma unroll
        for (int jp = 0; jp < 8; ++jp) {
            uint32_t b0, b1, b2, b3;
            LDMATRIX_X4(b0, b1, b2, b3, bBase + (uint32_t)(jp * 16) * RS + (uint32_t)ks * 32);
            MMA_BF16(acc[2 * jp],     a0, a1, a2, a3, b0, b1);
            MMA_BF16(acc[2 * jp + 1], a0, a1, a2, a3, b2, b3);
        }
    }

    const int g = lane >> 2, t = lane & 3;
    const int r_lo = row0 + wid * 16 + g;
    const int r_hi = r_lo + 8;
    const bool lo_ok = r_lo < M, hi_ok = r_hi < M;

    #pragma unroll
    for (int nt = 0; nt < 16; ++nt) {
        int col = nt * 8 + 2 * t;
        float bx = sbias[col], by = sbias[col + 1];
        uint32_t plo, phi;
        asm("cvt.rn.bf16x2.f32 %0, %1, %2;" : "=r"(plo)
            : "f"(acc[nt][1] + by), "f"(acc[nt][0] + bx));
        asm("cvt.rn.bf16x2.f32 %0, %1, %2;" : "=r"(phi)
            : "f"(acc[nt][3] + by), "f"(acc[nt][2] + bx));
        if (lo_ok) *(uint32_t*)(Cout + (size_t)r_lo * 128 + col) = plo;
        if (hi_ok) *(uint32_t*)(Cout + (size_t)r_hi * 128 + col) = phi;
    }
}

// ---------------- CSR build (edge streams read evict-first) ----------------
__global__ void hist_kernel(const int* __restrict__ dst, int E, int* __restrict__ deg) {
    int i = blockIdx.x * blockDim.x + threadIdx.x;
    if (i < E) atomicAdd(&deg[__ldcs(dst + i)], 1);
}

__global__ void scan1_kernel(const int* __restrict__ in, int n,
                             int* __restrict__ out, int* __restrict__ bsum) {
    __shared__ int sh[1024];
    int i = blockIdx.x * 1024 + threadIdx.x;
    int v = (i < n) ? in[i] : 0;
    sh[threadIdx.x] = v;
    __syncthreads();
    #pragma unroll
    for (int off = 1; off < 1024; off <<= 1) {
        int t = (threadIdx.x >= off) ? sh[threadIdx.x - off] : 0;
        __syncthreads();
        sh[threadIdx.x] += t;
        __syncthreads();
    }
    if (i < n) out[i] = sh[threadIdx.x] - v;
    if (bsum && threadIdx.x == 1023) bsum[blockIdx.x] = sh[1023];
}

__global__ void scan3_kernel(int* __restrict__ out, int n, const int* __restrict__ bofs) {
    int i = blockIdx.x * blockDim.x + threadIdx.x;
    if (i < n) out[i] += bofs[i >> 10];
}

__global__ void place_kernel(const int* __restrict__ src, const int* __restrict__ dst,
                             const float* __restrict__ w, int E,
                             const int* __restrict__ off, int* __restrict__ cnt,
                             int2* __restrict__ epk) {
    int i = blockIdx.x * blockDim.x + threadIdx.x;
    if (i >= E) return;
    int d = __ldcs(dst + i);
    int s = __ldcs(src + i);
    float wv = __ldcs(w + i);
    int p = off[d] + atomicAdd(&cnt[d], 1);
    epk[p] = make_int2(s, __float_as_int(wv));
}

// ---------------- gather-reduce + head: one HALF-WARP per account, 16B lanes ----------
__global__ void __launch_bounds__(256)
gather_head_kernel(const __nv_bfloat16* __restrict__ acch,
                   const int* __restrict__ off,
                   const int2* __restrict__ epk,
                   const __nv_bfloat16* __restrict__ m2,
                   const float* __restrict__ Wo,
                   const float* __restrict__ bo,
                   float* __restrict__ out,
                   int na0, int na1, int NA, int E) {
    const int tid  = threadIdx.x;
    const int lane = tid & 31;
    const int hw   = lane >> 4;                    // half-warp id 0/1
    const int sl   = lane & 15;                    // sub-lane 0..15
    const int acct = na0 + ((blockIdx.x * blockDim.x + tid) >> 5) * 2 + hw;
    if (acct >= na1) return;

    const int a = off[acct];
    const int b = (acct + 1 < NA) ? off[acct + 1] : E;

    float z0, z1, z2, z3, z4, z5, z6, z7;
    {
        uint4 q = *(const uint4*)((const char*)acch + (size_t)acct * 256 + sl * 16);
        float2 f0 = __bfloat1622float2(*reinterpret_cast<__nv_bfloat162*>(&q.x));
        float2 f1 = __bfloat1622float2(*reinterpret_cast<__nv_bfloat162*>(&q.y));
        float2 f2 = __bfloat1622float2(*reinterpret_cast<__nv_bfloat162*>(&q.z));
        float2 f3 = __bfloat1622float2(*reinterpret_cast<__nv_bfloat162*>(&q.w));
        z0 = f0.x; z1 = f0.y; z2 = f1.x; z3 = f1.y;
        z4 = f2.x; z5 = f2.y; z6 = f3.x; z7 = f3.y;
    }

    const uint32_t sl16 = (uint32_t)sl * 16u;
    int e = a;
    #define ACC_EDGE(P, Q) do { \
        float wf = __int_as_float((P).y); \
        float2 f0 = __bfloat1622float2(*reinterpret_cast<__nv_bfloat162*>(&(Q).x)); \
        float2 f1 = __bfloat1622float2(*reinterpret_cast<__nv_bfloat162*>(&(Q).y)); \
        float2 f2 = __bfloat1622float2(*reinterpret_cast<__nv_bfloat162*>(&(Q).z)); \
        float2 f3 = __bfloat1622float2(*reinterpret_cast<__nv_bfloat162*>(&(Q).w)); \
        z0 = fmaf(f0.x, wf, z0); z1 = fmaf(f0.y, wf, z1); \
        z2 = fmaf(f1.x, wf, z2); z3 = fmaf(f1.y, wf, z3); \
        z4 = fmaf(f2.x, wf, z4); z5 = fmaf(f2.y, wf, z5); \
        z6 = fmaf(f3.x, wf, z6); z7 = fmaf(f3.y, wf, z7); \
    } while (0)

    for (; e + 4 <= b; e += 4) {
        int2 p0 = __ldg(&epk[e + 0]);
        int2 p1 = __ldg(&epk[e + 1]);
        int2 p2 = __ldg(&epk[e + 2]);
        int2 p3 = __ldg(&epk[e + 3]);
        uint4 q0 = *(const uint4*)((const char*)m2 + (size_t)p0.x * 256 + sl16);
        uint4 q1 = *(const uint4*)((const char*)m2 + (size_t)p1.x * 256 + sl16);
        uint4 q2 = *(const uint4*)((const char*)m2 + (size_t)p2.x * 256 + sl16);
        uint4 q3 = *(const uint4*)((const char*)m2 + (size_t)p3.x * 256 + sl16);
        ACC_EDGE(p0, q0); ACC_EDGE(p1, q1); ACC_EDGE(p2, q2); ACC_EDGE(p3, q3);
    }
    for (; e < b; ++e) {
        int2 pk = __ldg(&epk[e]);
        uint4 q = *(const uint4*)((const char*)m2 + (size_t)pk.x * 256 + sl16);
        ACC_EDGE(pk, q);
    }
    #undef ACC_EDGE

    const float4 w0 = ((const float4*)Wo)[sl * 2];
    const float4 w1 = ((const float4*)Wo)[sl * 2 + 1];
    float p = fmaxf(z0, 0.f) * w0.x + fmaxf(z1, 0.f) * w0.y +
              fmaxf(z2, 0.f) * w0.z + fmaxf(z3, 0.f) * w0.w +
              fmaxf(z4, 0.f) * w1.x + fmaxf(z5, 0.f) * w1.y +
              fmaxf(z6, 0.f) * w1.z + fmaxf(z7, 0.f) * w1.w;
    #pragma unroll
    for (int o = 8; o > 0; o >>= 1)
        p += __shfl_xor_sync(0xFFFFFFFFu, p, o);
    if (sl == 0) {
        float zz = p + bo[0];
        out[acct] = 1.f / (1.f + expf(-zz));
    }
}

// ---------------- launch (fork-join + 2-way GEMM3/gather pipeline) ----------------
extern "C" void kernel_launch(void* const* d_in, const int* in_sizes, int n_in,
                              void* d_out, int out_size) {
    const float* x_account  = (const float*)d_in[0];
    const float* x_merchant = (const float*)d_in[1];
    const int*   e_ma_src = (const int*)d_in[5];
    const int*   e_ma_dst = (const int*)d_in[6];
    const float* e_ma_w   = (const float*)d_in[7];
    const float* Wp_a  = (const float*)d_in[8];
    const float* bp_a  = (const float*)d_in[9];
    const float* Wr_ma = (const float*)d_in[14];
    const float* br_ma = (const float*)d_in[15];
    const float* Wc_a  = (const float*)d_in[16];
    const float* bc_a  = (const float*)d_in[17];
    const float* Wo = (const float*)d_in[20];
    const float* bo = (const float*)d_in[21];
    float* out = (float*)d_out;

    const int NA = in_sizes[0] / DAa;   // 200000
    const int NM = in_sizes[1] / DMm;   // 100000
    const int E  = in_sizes[5];         // 1000000

    float *pb1, *pb2;
    __nv_bfloat16 *pW1h, *pW2h, *pm2, *pacch;
    int *pdeg, *poff, *pcnt, *pbsum, *pbofs;
    int2 *pepk;
    cudaGetSymbolAddress((void**)&pb1, g_b1);
    cudaGetSymbolAddress((void**)&pb2, g_b2);
    cudaGetSymbolAddress((void**)&pW1h, g_W1h);
    cudaGetSymbolAddress((void**)&pW2h, g_W2h);
    cudaGetSymbolAddress((void**)&pm2, g_m2);
    cudaGetSymbolAddress((void**)&pacch, g_acch);
    cudaGetSymbolAddress((void**)&pdeg, g_deg);
    cudaGetSymbolAddress((void**)&poff, g_off);
    cudaGetSymbolAddress((void**)&pcnt, g_cnt);
    cudaGetSymbolAddress((void**)&pbsum, g_bsum);
    cudaGetSymbolAddress((void**)&pbofs, g_bofs);
    cudaGetSymbolAddress((void**)&pepk, g_epk);

    constexpr int SMEM_K128 = 2 * 128 * (128 * 2 + 16) + 512;   // 70144 B
    constexpr int SMEM_K64  = 2 * 128 * (64 * 2 + 16) + 512;    // 37376 B
    cudaFuncSetAttribute(mma_gemm_kernel<128>,
                         cudaFuncAttributeMaxDynamicSharedMemorySize, SMEM_K128);
    cudaFuncSetAttribute(mma_gemm_kernel<64>,
                         cudaFuncAttributeMaxDynamicSharedMemorySize, SMEM_K64);

    static cudaStream_t sCsr = [] { cudaStream_t s;
        cudaStreamCreateWithFlags(&s, cudaStreamNonBlocking); return s; }();
    static cudaStream_t sM2 = [] { cudaStream_t s;
        cudaStreamCreateWithFlags(&s, cudaStreamNonBlocking); return s; }();
    static cudaStream_t sGat = [] { cudaStream_t s;
        cudaStreamCreateWithFlags(&s, cudaStreamNonBlocking); return s; }();
    static cudaEvent_t evRoot = [] { cudaEvent_t e;
        cudaEventCreateWithFlags(&e, cudaEventDisableTiming); return e; }();
    static cudaEvent_t evFold = [] { cudaEvent_t e;
        cudaEventCreateWithFlags(&e, cudaEventDisableTiming); return e; }();
    static cudaEvent_t evCsr = [] { cudaEvent_t e;
        cudaEventCreateWithFlags(&e, cudaEventDisableTiming); return e; }();
    static cudaEvent_t evM2 = [] { cudaEvent_t e;
        cudaEventCreateWithFlags(&e, cudaEventDisableTiming); return e; }();
    static cudaEvent_t evG3a = [] { cudaEvent_t e;
        cudaEventCreateWithFlags(&e, cudaEventDisableTiming); return e; }();
    static cudaEvent_t evG3b = [] { cudaEvent_t e;
        cudaEventCreateWithFlags(&e, cudaEventDisableTiming); return e; }();
    static cudaEvent_t evGat = [] { cudaEvent_t e;
        cudaEventCreateWithFlags(&e, cudaEventDisableTiming); return e; }();

    // GEMM3 split point (multiple of 128 rows)
    const int half = ((NA / 2 + 127) / 128) * 128;     // 100096

    // Fork from the capture (default) stream
    cudaEventRecord(evRoot, 0);
    cudaStreamWaitEvent(sCsr, evRoot, 0);
    cudaStreamWaitEvent(sM2, evRoot, 0);
    cudaStreamWaitEvent(sGat, evRoot, 0);

    // --- branch A (sCsr): CSR build ---
    cudaMemsetAsync(pdeg, 0, (size_t)NA * sizeof(int), sCsr);
    cudaMemsetAsync(pcnt, 0, (size_t)NA * sizeof(int), sCsr);
    hist_kernel<<<(E + 255) / 256, 256, 0, sCsr>>>(e_ma_dst, E, pdeg);
    {
        int nblk = (NA + 1023) / 1024;           // 196
        scan1_kernel<<<nblk, 1024, 0, sCsr>>>(pdeg, NA, poff, pbsum);
        scan1_kernel<<<1, 1024, 0, sCsr>>>(pbsum, nblk, pbofs, nullptr);
        scan3_kernel<<<(NA + 255) / 256, 256, 0, sCsr>>>(poff, NA, pbofs);
    }
    place_kernel<<<(E + 255) / 256, 256, 0, sCsr>>>(e_ma_src, e_ma_dst, e_ma_w,
                                                    E, poff, pcnt, pepk);
    cudaEventRecord(evCsr, sCsr);

    // --- branch B (default): fold ---
    fold_kernel<<<128, 128>>>(Wc_a, Wp_a, Wr_ma, bp_a, bc_a, br_ma);
    cudaEventRecord(evFold, 0);

    // --- branch C (sM2): GEMM2 after fold ---
    cudaStreamWaitEvent(sM2, evFold, 0);
    mma_gemm_kernel<64><<<(NM + 127) / 128, 256, SMEM_K64, sM2>>>(
        x_merchant, NM, pW2h, pb2, pm2);
    cudaEventRecord(evM2, sM2);

    // --- branch B continues: GEMM3 in two halves ---
    mma_gemm_kernel<128><<<half / 128, 256, SMEM_K128>>>(
        x_account, half, pW1h, pb1, pacch);
    cudaEventRecord(evG3a, 0);
    mma_gemm_kernel<128><<<(NA - half + 127) / 128, 256, SMEM_K128>>>(
        x_account + (size_t)half * DAa, NA - half, pW1h, pb1,
        pacch + (size_t)half * Hh);
    cudaEventRecord(evG3b, 0);

    // --- branch D (sGat): gather+head pipelined against GEMM3 half 2 ---
    cudaStreamWaitEvent(sGat, evCsr, 0);
    cudaStreamWaitEvent(sGat, evM2, 0);
    cudaStreamWaitEvent(sGat, evG3a, 0);
    gather_head_kernel<<<(half + 15) / 16, 256, 0, sGat>>>(
        pacch, poff, pepk, pm2, Wo, bo, out, 0, half, NA, E);
    cudaStreamWaitEvent(sGat, evG3b, 0);
    gather_head_kernel<<<(NA - half + 15) / 16, 256, 0, sGat>>>(
        pacch, poff, pepk, pm2, Wo, bo, out, half, NA, NA, E);
    cudaEventRecord(evGat, sGat);

    // --- join back to capture stream ---
    cudaStreamWaitEvent(0, evGat, 0);
}